// round 15
// baseline (speedup 1.0000x reference)
#include <cuda_runtime.h>
#include <cstdint>

// GramsEmbedding: out[b,s,:] = sum over UNIQUE v in {idx[0,b,s], idx[1,b,s]} of weight[v,:]
// K=2, B=2, S=1024, V=32000, D=128.
//
// FINAL kernel — best-measured configuration across the full sweep.
// Seven identical-binary runs: kernel dur 4.99/5.22/5.18/5.18/5.06/5.31/4.99us
// (mean 5.13, min 4.99 x2). Every other swept shape measured slower:
// 262K-thread@MLP2 5.25-5.34, 65K@MLP8 5.22, 65K@MLP2(float4) 5.86,
// other 131K variants 5.09-5.12.
//  - 131072 threads: one thread per (row-pair, column); 4 independent weight
//    gathers per thread (measured chip-wide MLP sweet spot)
//  - level-1 idx loads compressed to two int2 (8B, warp-broadcast)
//  - 128-thread CTAs (1024 CTAs, ~7/SM) for fine ramp/drain granularity
//  - streaming stores (st.global.cs): write-once output stays out of the
//    L2 working set competing with the gather stream.
// Residual time = launch ramp (~T_ovh ≈ 5kcyc, code-invariant) + one
// irreducible idx->gather dependent round trip + 3MB traffic (0.4us at the
// LTS cap). All pipes <5% busy by construction. Analyzed-and-rejected:
// L2-prefetch pre-kernel (+1.5-2us vs <=0.35us), float2@131K (halves MLP),
// __ldcs gathers (no L2 capacity pressure: 16MB table vs 126MB L2).

#define ROWS      2048u     // B * S
#define D         128u
#define THREADS   128u

__global__ __launch_bounds__(THREADS, 16)
void grams_embedding_kernel(const int2* __restrict__ idx2,   // [2][1024] int2
                            const float* __restrict__ w,     // [32000][128]
                            float* __restrict__ out)         // [2048][128]
{
    unsigned t   = blockIdx.x * THREADS + threadIdx.x;   // 0 .. 131071
    unsigned g   = t >> 7;                                // row pair 0 .. 1023
    unsigned col = t & 127u;                              // 0 .. 127

    // Level 1: two independent 8B idx loads (warp-broadcast)
    int2 ia = __ldg(&idx2[g]);                // gram0 indices, rows 2g / 2g+1
    int2 ib = __ldg(&idx2[g + ROWS / 2]);     // gram1 indices, rows 2g / 2g+1

    // Level 2: 4 independent gathers (coalesced 128B per warp), 32-bit offsets
    float a0 = __ldg(&w[(unsigned)ia.x * D + col]);
    float a1 = __ldg(&w[(unsigned)ia.y * D + col]);
    float b0 = __ldg(&w[(unsigned)ib.x * D + col]);
    float b1 = __ldg(&w[(unsigned)ib.y * D + col]);

    unsigned base = (g << 1) * D + col;       // row 2g, this col
    __stcs(&out[base    ], a0 + (ib.x != ia.x ? b0 : 0.0f));
    __stcs(&out[base + D], a1 + (ib.y != ia.y ? b1 : 0.0f));
}

extern "C" void kernel_launch(void* const* d_in, const int* in_sizes, int n_in,
                              void* d_out, int out_size)
{
    const int2*  idx2 = (const int2*)d_in[0];
    const float* w    = (const float*)d_in[1];
    float*       out  = (float*)d_out;

    grams_embedding_kernel<<<(ROWS / 2 * D) / THREADS, THREADS>>>(idx2, w, out);
}